// round 16
// baseline (speedup 1.0000x reference)
#include <cuda_runtime.h>
#include <cuda_fp16.h>
#include <cstdint>

#define LL 256
#define HC 256
#define NROWS (LL*LL)   // 65536

// ---------------- scratch (static device globals; no allocations) ----------
__device__ __align__(16) __half g_xs[NROWS*256];      // layernorm out split: [row][0:128 hi | 128:256 lo]
__device__ __align__(16) __half g_qs[NROWS*512];      // q split  [(s,h,r)][0:64 hi | 64:128 lo] (pre-scaled)
__device__ __align__(16) __half g_ks[NROWS*512];      // k split  same layout
__device__ __align__(16) __half g_vh[NROWS*256];      // v half   [(s,h,r)][c]
__device__ __align__(16) __half g_uh[NROWS*256];      // sigmoid gate half [(s,h,r)][c]
__device__ __align__(16) float  g_bias[4*NROWS];      // pair_bias + mask bias [h][q][v]
__device__ __align__(16) __half g_oh[NROWS*256];      // attention out half [s*256+q][h*64+c]
// pre-transposed / split weights [n][k] half
__device__ __align__(16) __half g_Wqt_h[256*128], g_Wqt_l[256*128];
__device__ __align__(16) __half g_Wkt_h[256*128], g_Wkt_l[256*128];
__device__ __align__(16) __half g_Wvt[256*128], g_Wut[256*128];
__device__ __align__(16) __half g_Wot[128*256];

// ---------------- mma / ldmatrix helpers ----------------
__device__ __forceinline__ uint32_t sm_addr(const void* p) {
    return (uint32_t)__cvta_generic_to_shared(p);
}
__device__ __forceinline__ void ldm_x4(uint32_t* r, uint32_t a) {
    asm volatile("ldmatrix.sync.aligned.m8n8.x4.shared.b16 {%0,%1,%2,%3}, [%4];"
                 : "=r"(r[0]), "=r"(r[1]), "=r"(r[2]), "=r"(r[3]) : "r"(a));
}
__device__ __forceinline__ void ldm_x4_t(uint32_t* r, uint32_t a) {
    asm volatile("ldmatrix.sync.aligned.m8n8.x4.trans.shared.b16 {%0,%1,%2,%3}, [%4];"
                 : "=r"(r[0]), "=r"(r[1]), "=r"(r[2]), "=r"(r[3]) : "r"(a));
}
__device__ __forceinline__ void mma_f16(float* c, const uint32_t* a, const uint32_t* b) {
    asm volatile("mma.sync.aligned.m16n8k16.row.col.f32.f16.f16.f32 "
                 "{%0,%1,%2,%3},{%4,%5,%6,%7},{%8,%9},{%0,%1,%2,%3};"
                 : "+f"(c[0]), "+f"(c[1]), "+f"(c[2]), "+f"(c[3])
                 : "r"(a[0]), "r"(a[1]), "r"(a[2]), "r"(a[3]), "r"(b[0]), "r"(b[1]));
}
template<int STRIDE>
__device__ __forceinline__ uint32_t qaddr(uint32_t base, int r0, int c0, int lane) {
    int t = lane >> 3, tr = lane & 7;
    return base + (uint32_t)(((r0 + tr + (t & 1) * 8) * STRIDE + c0 + (t >> 1) * 8) * 2);
}
__device__ __forceinline__ uint32_t pack2(float x, float y) {
    __half2 h = __floats2half2_rn(x, y);
    return *(uint32_t*)&h;
}

// ---------------- kernel 0: weight transpose + split ----------------
__global__ void prep_kernel(const float* __restrict__ Wq, const float* __restrict__ Wk,
                            const float* __restrict__ Wv, const float* __restrict__ Wu,
                            const float* __restrict__ Wo) {
    for (int idx = blockIdx.x * 256 + threadIdx.x; idx < 32768; idx += gridDim.x * 256) {
        int k = idx >> 8, n = idx & 255;
        float xq = Wq[idx]; __half hq = __float2half_rn(xq);
        g_Wqt_h[n*128+k] = hq; g_Wqt_l[n*128+k] = __float2half_rn(xq - __half2float(hq));
        float xk = Wk[idx]; __half hk = __float2half_rn(xk);
        g_Wkt_h[n*128+k] = hk; g_Wkt_l[n*128+k] = __float2half_rn(xk - __half2float(hk));
        g_Wvt[n*128+k] = __float2half_rn(Wv[idx]);
        g_Wut[n*128+k] = __float2half_rn(Wu[idx]);
        int k2 = idx >> 7, n2 = idx & 127;
        g_Wot[n2*256+k2] = __float2half_rn(Wo[idx]);
    }
}

// ---------------- kernel 1: layernorm + fused pair_bias/mask bias ----------
__global__ __launch_bounds__(256) void ln_kernel(const float* __restrict__ in,
                                                 const float* __restrict__ gamma,
                                                 const float* __restrict__ beta,
                                                 const float* __restrict__ Wb,
                                                 const float* __restrict__ mask) {
    int row  = blockIdx.x * 8 + (threadIdx.x >> 5);
    int lane = threadIdx.x & 31;
    float4 v = reinterpret_cast<const float4*>(in)[(size_t)row * 32 + lane];
    float s  = v.x + v.y + v.z + v.w;
    float ss = v.x*v.x + v.y*v.y + v.z*v.z + v.w*v.w;
#pragma unroll
    for (int o = 16; o; o >>= 1) {
        s  += __shfl_xor_sync(0xffffffffu, s,  o);
        ss += __shfl_xor_sync(0xffffffffu, ss, o);
    }
    float mu  = s * (1.f / 128.f);
    float var = fmaxf(ss * (1.f / 128.f) - mu * mu, 0.f);
    float inv = rsqrtf(var + 1e-5f);
    float4 g = reinterpret_cast<const float4*>(gamma)[lane];
    float4 b = reinterpret_cast<const float4*>(beta)[lane];
    float o4[4];
    o4[0] = (v.x - mu) * inv * g.x + b.x;
    o4[1] = (v.y - mu) * inv * g.y + b.y;
    o4[2] = (v.z - mu) * inv * g.z + b.z;
    o4[3] = (v.w - mu) * inv * g.w + b.w;
    // split-half output
    __half h[4]; float l[4];
#pragma unroll
    for (int i = 0; i < 4; i++) { h[i] = __float2half_rn(o4[i]); l[i] = o4[i] - __half2float(h[i]); }
    uint2 hi2 = make_uint2(pack2(__half2float(h[0]), __half2float(h[1])),
                           pack2(__half2float(h[2]), __half2float(h[3])));
    uint2 lo2 = make_uint2(pack2(l[0], l[1]), pack2(l[2], l[3]));
    uint2* dst = (uint2*)(g_xs + (size_t)row * 256);
    dst[lane] = hi2;
    dst[32 + lane] = lo2;
    // fused pair_bias: b_h = sum_d x[d] * Wb[d*4+h], warp-reduced
    int d0 = lane * 4;
    float4 w0 = *(const float4*)(Wb + (d0+0)*4);
    float4 w1 = *(const float4*)(Wb + (d0+1)*4);
    float4 w2 = *(const float4*)(Wb + (d0+2)*4);
    float4 w3 = *(const float4*)(Wb + (d0+3)*4);
    float b0 = o4[0]*w0.x + o4[1]*w1.x + o4[2]*w2.x + o4[3]*w3.x;
    float b1 = o4[0]*w0.y + o4[1]*w1.y + o4[2]*w2.y + o4[3]*w3.y;
    float b2 = o4[0]*w0.z + o4[1]*w1.z + o4[2]*w2.z + o4[3]*w3.z;
    float b3 = o4[0]*w0.w + o4[1]*w1.w + o4[2]*w2.w + o4[3]*w3.w;
#pragma unroll
    for (int o = 16; o; o >>= 1) {
        b0 += __shfl_xor_sync(0xffffffffu, b0, o);
        b1 += __shfl_xor_sync(0xffffffffu, b1, o);
        b2 += __shfl_xor_sync(0xffffffffu, b2, o);
        b3 += __shfl_xor_sync(0xffffffffu, b3, o);
    }
    if (lane < 4) {
        float bsel = (lane == 0) ? b0 : (lane == 1) ? b1 : (lane == 2) ? b2 : b3;
        g_bias[(size_t)lane * 65536 + row] = bsel + 1e9f * (mask[row] - 1.f);
    }
}

// ---------------- kernel 3: split projection GEMM (Q,K) -- R10 form ----------
// CTA tile 128m x 64n, FULL K=128 resident (hi|lo). One sync, 8 k-steps.
#define PROJS_SMEM (128*264*2 + 2*64*136*2)   // 67584 + 34816 = 102400
__global__ __launch_bounds__(256) void proj_split_kernel() {
    extern __shared__ char smem[];
    __half* As = (__half*)smem;                       // [128][264]: 0..127 hi k, 128..255 lo k
    __half* Bh = (__half*)(smem + 128*264*2);         // [64][136]
    __half* Bl = (__half*)(smem + 128*264*2 + 64*136*2);
    int bm = blockIdx.x, bn = blockIdx.y;             // bn 0..7
    int mat = bn >> 2;                                // 0:q 1:k
    int ncol0 = (bn & 3) * 64;
    const __half* Wh = mat ? g_Wkt_h : g_Wqt_h;
    const __half* Wl = mat ? g_Wkt_l : g_Wqt_l;
    int tid = threadIdx.x, lane = tid & 31, w = tid >> 5;
    int g = lane >> 2, tig = lane & 3;
    int wm = (w & 3) * 32, wn = (w >> 2) * 32;
    uint32_t asb = sm_addr(As), bhb = sm_addr(Bh), blb = sm_addr(Bl);

    // A: 128 rows x 32 uint4 (row layout identical to g_xs)
#pragma unroll
    for (int t = 0; t < 16; t++) {
        int idx = tid + 256 * t;
        int row = idx >> 5, cc = idx & 31;
        *(uint4*)&As[row*264 + cc*8] =
            reinterpret_cast<const uint4*>(g_xs)[(size_t)(bm*128+row)*32 + cc];
    }
    // B: 64 rows x 16 uint4 each of hi/lo
#pragma unroll
    for (int t = 0; t < 4; t++) {
        int idx = tid + 256 * t;
        int row = idx >> 4, cc = idx & 15;
        *(uint4*)&Bh[row*136 + cc*8] =
            reinterpret_cast<const uint4*>(Wh)[(size_t)(ncol0+row)*16 + cc];
        *(uint4*)&Bl[row*136 + cc*8] =
            reinterpret_cast<const uint4*>(Wl)[(size_t)(ncol0+row)*16 + cc];
    }
    __syncthreads();

    float c[2][4][4] = {};
#pragma unroll
    for (int ki = 0; ki < 8; ki++) {
        uint32_t ah[2][4], al[2][4];
#pragma unroll
        for (int mt = 0; mt < 2; mt++) {
            ldm_x4(ah[mt], qaddr<264>(asb, wm + mt*16, ki*16, lane));
            ldm_x4(al[mt], qaddr<264>(asb, wm + mt*16, 128 + ki*16, lane));
        }
#pragma unroll
        for (int nf = 0; nf < 2; nf++) {
            uint32_t bh[4], bl[4];
            ldm_x4(bh, qaddr<136>(bhb, wn + nf*16, ki*16, lane));
            ldm_x4(bl, qaddr<136>(blb, wn + nf*16, ki*16, lane));
            uint32_t b0h[2] = {bh[0], bh[2]}, b1h[2] = {bh[1], bh[3]};
            uint32_t b0l[2] = {bl[0], bl[2]}, b1l[2] = {bl[1], bl[3]};
#pragma unroll
            for (int mt = 0; mt < 2; mt++) {
                mma_f16(c[mt][nf*2],   ah[mt], b0h);
                mma_f16(c[mt][nf*2],   al[mt], b0h);
                mma_f16(c[mt][nf*2],   ah[mt], b0l);
                mma_f16(c[mt][nf*2+1], ah[mt], b1h);
                mma_f16(c[mt][nf*2+1], al[mt], b1h);
                mma_f16(c[mt][nf*2+1], ah[mt], b1l);
            }
        }
    }
    // epilogue: split fp32 -> (hi,lo) half pairs, scatter to [s,h,r,c] layout
    __half* dst = mat ? g_ks : g_qs;
    float scale = mat ? 1.f : 0.125f;
#pragma unroll
    for (int mt = 0; mt < 2; mt++) {
#pragma unroll
        for (int rs = 0; rs < 2; rs++) {
            int m = bm*128 + wm + mt*16 + g + rs*8;
            int si = m >> 8, rr = m & 255;
#pragma unroll
            for (int ni = 0; ni < 4; ni++) {
                int col = ncol0 + wn + ni*8 + tig*2;
                int head = col >> 6, cc = col & 63;
                size_t drow = ((size_t)(si*4 + head))*256 + rr;
                float v0 = c[mt][ni][rs*2+0] * scale;
                float v1 = c[mt][ni][rs*2+1] * scale;
                __half h0 = __float2half_rn(v0), h1 = __float2half_rn(v1);
                float l0 = v0 - __half2float(h0), l1 = v1 - __half2float(h1);
                *(uint32_t*)(dst + drow*128 + cc)      = pack2(__half2float(h0), __half2float(h1));
                *(uint32_t*)(dst + drow*128 + 64 + cc) = pack2(l0, l1);
            }
        }
    }
}

// ---------------- kernel 4: single-fp16 projection GEMM (V,U) ----------------
// CTA tile 128x128, FULL K=128 resident; minblocks 3 -> 24 warps/SM.
#define PROJ1_SMEM (2*128*136*2)   // 69632
__global__ __launch_bounds__(256, 3) void proj_single_kernel(const float* __restrict__ bu) {
    extern __shared__ char smem[];
    __half* As = (__half*)smem;                   // [128][136]
    __half* Bs = (__half*)(smem + 128*136*2);     // [128][136]
    int bm = blockIdx.x, bn = blockIdx.y;
    int mat = bn >> 1;                  // 0:v 1:u
    int ncol0 = (bn & 1) * 128;
    const __half* W = mat ? g_Wut : g_Wvt;
    int tid = threadIdx.x, lane = tid & 31, w = tid >> 5;
    int g = lane >> 2, tig = lane & 3;
    int wm = (w & 3) * 32, wn = (w >> 2) * 64;
    uint32_t asb = sm_addr(As), bsb = sm_addr(Bs);

#pragma unroll
    for (int t = 0; t < 8; t++) {
        int idx = tid + 256 * t;
        int row = idx >> 4, cc = idx & 15;
        *(uint4*)&As[row*136 + cc*8] =
            reinterpret_cast<const uint4*>(g_xs)[(size_t)(bm*128+row)*32 + cc];   // hi half only
        *(uint4*)&Bs[row*136 + cc*8] =
            reinterpret_cast<const uint4*>(W)[(size_t)(ncol0+row)*16 + cc];
    }
    __syncthreads();

    float c[2][8][4] = {};
#pragma unroll
    for (int ki = 0; ki < 8; ki++) {
        uint32_t a[2][4];
#pragma unroll
        for (int mt = 0; mt < 2; mt++)
            ldm_x4(a[mt], qaddr<136>(asb, wm + mt*16, ki*16, lane));
#pragma unroll
        for (int nf = 0; nf < 4; nf++) {
            uint32_t b[4];
            ldm_x4(b, qaddr<136>(bsb, wn + nf*16, ki*16, lane));
            uint32_t b0[2] = {b[0], b[2]}, b1[2] = {b[1], b[3]};
#pragma unroll
            for (int mt = 0; mt < 2; mt++) {
                mma_f16(c[mt][nf*2],   a[mt], b0);
                mma_f16(c[mt][nf*2+1], a[mt], b1);
            }
        }
    }
#pragma unroll
    for (int mt = 0; mt < 2; mt++) {
#pragma unroll
        for (int rs = 0; rs < 2; rs++) {
            int m = bm*128 + wm + mt*16 + g + rs*8;
            int si = m >> 8, rr = m & 255;
#pragma unroll
            for (int ni = 0; ni < 8; ni++) {
                int col = ncol0 + wn + ni*8 + tig*2;
                int head = col >> 6, cc = col & 63;
                size_t drow = ((size_t)(si*4 + head))*256 + rr;
                float v0 = c[mt][ni][rs*2+0], v1 = c[mt][ni][rs*2+1];
                if (mat == 0) {
                    *(uint32_t*)(g_vh + drow*64 + cc) = pack2(v0, v1);
                } else {
                    float2 b2 = *(const float2*)(bu + col);
                    float u0 = 1.f / (1.f + __expf(-(v0 + b2.x)));
                    float u1 = 1.f / (1.f + __expf(-(v1 + b2.y)));
                    *(uint32_t*)(g_uh + drow*64 + cc) = pack2(u0, u1);
                }
            }
        }
    }
}

// ---------------- kernel 5: attention per (s, h, q-tile of 64) ----------------
// smem 91.4KB -> 2 CTAs/SM.
#define AT_QB 17408
#define AT_PH 17408
#define AT_VS 52224
#define AT_WM 89088
#define AT_WS 90112
#define AT_RI 91136
#define ATTN_SMEM 91392
__global__ __launch_bounds__(512, 2) void attn_kernel() {
    extern __shared__ char smem[];
    __half* Ks = (__half*)smem;
    __half* Qb = (__half*)(smem + AT_QB);
    __half* Ph = (__half*)(smem + AT_PH);
    __half* Vs = (__half*)(smem + AT_VS);
    float* wmax = (float*)(smem + AT_WM);
    float* wsum = (float*)(smem + AT_WS);
    float* rinv = (float*)(smem + AT_RI);

    int b = blockIdx.x;
    int s = b >> 4, h = (b >> 2) & 3, qt = b & 3;
    int tid = threadIdx.x, lane = tid & 31, w = tid >> 5;
    int g = lane >> 2, tig = lane & 3;
    size_t base = ((size_t)(s*4 + h)) * 256;

#pragma unroll
    for (int t = 0; t < 2; t++) {
        int idx = tid + 512 * t;
        int r = idx >> 4, cc = idx & 15;
        *(uint4*)&Ks[r*136 + cc*8] =
            reinterpret_cast<const uint4*>(g_ks)[(base + qt*64 + r)*16 + cc];
    }

    int wq = w & 3, wv = w >> 2;
    int q0 = wq * 16;
    uint32_t ksb = sm_addr(Ks), qbb = sm_addr(Qb);
    float c[8][4] = {};
#pragma unroll
    for (int p = 0; p < 2; p++) {
        if (p) __syncthreads();
#pragma unroll
        for (int t = 0; t < 4; t++) {
            int idx = tid + 512 * t;
            int r = idx >> 4, cc = idx & 15;
            *(uint4*)&Qb[r*136 + cc*8] =
                reinterpret_cast<const uint4*>(g_qs)[(base + p*128 + r)*16 + cc];
        }
        __syncthreads();
#pragma unroll
        for (int kt = 0; kt < 4; kt++) {
            uint32_t ah[4], al[4];
            ldm_x4(ah, qaddr<136>(ksb, q0, kt*16, lane));
            ldm_x4(al, qaddr<136>(ksb, q0, 64 + kt*16, lane));
#pragma unroll
            for (int nf = 0; nf < 2; nf++) {
                uint32_t bh[4], bl[4];
                ldm_x4(bh, qaddr<136>(qbb, wv*32 + nf*16, kt*16, lane));
                ldm_x4(bl, qaddr<136>(qbb, wv*32 + nf*16, 64 + kt*16, lane));
                uint32_t b0h[2] = {bh[0], bh[2]}, b1h[2] = {bh[1], bh[3]};
                uint32_t b0l[2] = {bl[0], bl[2]}, b1l[2] = {bl[1], bl[3]};
                mma_f16(c[p*4 + nf*2],   ah, b0h);
                mma_f16(c[p*4 + nf*2],   al, b0h);
                mma_f16(c[p*4 + nf*2],   ah, b0l);
                mma_f16(c[p*4 + nf*2+1], ah, b1h);
                mma_f16(c[p*4 + nf*2+1], al, b1h);
                mma_f16(c[p*4 + nf*2+1], ah, b1l);
            }
        }
    }

    const float* bp = g_bias + ((size_t)h*256 + qt*64 + q0) * 256;
    float m0 = -3e38f, m1 = -3e38f;
#pragma unroll
    for (int ni = 0; ni < 8; ni++) {
        int v = (ni >> 2)*128 + wv*32 + (ni & 3)*8 + tig*2;
        float2 b0 = *(const float2*)(bp + (size_t)g*256 + v);
        float2 b1 = *(const float2*)(bp + (size_t)(g+8)*256 + v);
        c[ni][0] += b0.x; c[ni][1] += b0.y; c[ni][2] += b1.x; c[ni][3] += b1.y;
        m0 = fmaxf(m0, fmaxf(c[ni][0], c[ni][1]));
        m1 = fmaxf(m1, fmaxf(c[ni][2], c[ni][3]));
    }
    m0 = fmaxf(m0, __shfl_xor_sync(~0u, m0, 1)); m0 = fmaxf(m0, __shfl_xor_sync(~0u, m0, 2));
    m1 = fmaxf(m1, __shfl_xor_sync(~0u, m1, 1)); m1 = fmaxf(m1, __shfl_xor_sync(~0u, m1, 2));
    if (tig == 0) { wmax[wv*64 + q0 + g] = m0; wmax[wv*64 + q0 + g + 8] = m1; }
    __syncthreads();

#pragma unroll
    for (int t = 0; t < 4; t++) {
        int idx = tid + 512 * t;
        int r = idx >> 3, cc = idx & 7;
        *(uint4*)&Vs[r*72 + cc*8] =
            reinterpret_cast<const uint4*>(g_vh)[(base + r)*8 + cc];
    }

    float M0 = fmaxf(fmaxf(wmax[q0+g],     wmax[64+q0+g]),
                     fmaxf(wmax[128+q0+g], wmax[192+q0+g]));
    float M1 = fmaxf(fmaxf(wmax[q0+g+8],     wmax[64+q0+g+8]),
                     fmaxf(wmax[128+q0+g+8], wmax[192+q0+g+8]));
    float s0 = 0.f, s1 = 0.f;
#pragma unroll
    for (int ni = 0; ni < 8; ni++) {
        c[ni][0] = __expf(c[ni][0] - M0); c[ni][1] = __expf(c[ni][1] - M0);
        c[ni][2] = __expf(c[ni][2] - M1); c[ni][3] = __expf(c[ni][3] - M1);
        s0 += c[ni][0] + c[ni][1];
        s1 += c[ni][2] + c[ni][3];
        int v = (ni >> 2)*128 + wv*32 + (ni & 3)*8 + tig*2;
        *(uint32_t*)&Ph[(q0+g)*264 + v]   = pack2(c[ni][0], c[ni][1]);
        *(uint32_t*)&Ph[(q0+g+8)*264 + v] = pack2(c[ni][2], c[ni][3]);
    }
    s0 += __shfl_xor_sync(~0u, s0, 1); s0 += __shfl_xor_sync(~0u, s0, 2);
    s1 += __shfl_xor_sync(~0u, s1, 1); s1 += __shfl_xor_sync(~0u, s1, 2);
    if (tig == 0) { wsum[wv*64 + q0 + g] = s0; wsum[wv*64 + q0 + g + 8] = s1; }
    __syncthreads();
    if (tid < 64)
        rinv[tid] = 1.f / (wsum[tid] + wsum[64+tid] + wsum[128+tid] + wsum[192+tid]);
    __syncthreads();

    int wq2 = w & 3, wc = w >> 2;
    int pq0 = wq2 * 16, c0 = wc * 16;
    uint32_t phb = sm_addr(Ph), vsb = sm_addr(Vs);
    float oc[2][4] = {};
#pragma unroll
    for (int kt = 0; kt < 16; kt++) {
        uint32_t a[4], bt[4];
        ldm_x4(a, qaddr<264>(phb, pq0, kt*16, lane));
        ldm_x4_t(bt, qaddr<72>(vsb, kt*16, c0, lane));
        uint32_t f0[2] = {bt[0], bt[1]}, f1[2] = {bt[2], bt[3]};
        mma_f16(oc[0], a, f0);
        mma_f16(oc[1], a, f1);
    }
    {
        float rv0 = rinv[pq0 + g], rv1 = rinv[pq0 + g + 8];
        int qgA = qt*64 + pq0 + g, qgB = qgA + 8;
#pragma unroll
        for (int j = 0; j < 2; j++) {
            int ccol = c0 + j*8 + tig*2;
            float2 u0 = __half22float2(*(const __half2*)(g_uh + (base + qgA)*64 + ccol));
            float2 u1 = __half22float2(*(const __half2*)(g_uh + (base + qgB)*64 + ccol));
            float oA0 = oc[j][0] * rv0 * u0.x;
            float oA1 = oc[j][1] * rv0 * u0.y;
            float oB0 = oc[j][2] * rv1 * u1.x;
            float oB1 = oc[j][3] * rv1 * u1.y;
            *(uint32_t*)(g_oh + ((size_t)(s*256 + qgA))*256 + h*64 + ccol) = pack2(oA0, oA1);
            *(uint32_t*)(g_oh + ((size_t)(s*256 + qgB))*256 + h*64 + ccol) = pack2(oB0, oB1);
        }
    }
}

// ---------------- kernel 6: output GEMM (single fp16, half A input) ----------
#define OUT_SMEM (128*136*2*2)
__global__ __launch_bounds__(256) void out_kernel(const float* __restrict__ bo,
                                                  const float* __restrict__ mask,
                                                  float* __restrict__ out) {
    extern __shared__ char smem[];
    __half* As = (__half*)smem;                  // [128][136]
    __half* Bs = (__half*)(smem + 128*136*2);    // [128][136]
    int bm = blockIdx.x;
    int tid = threadIdx.x, lane = tid & 31, w = tid >> 5;
    int g = lane >> 2, tig = lane & 3;
    int wm = (w & 3) * 32, wn = (w >> 2) * 64;
    uint32_t asb = sm_addr(As), bsb = sm_addr(Bs);
    float c[2][8][4] = {};
    for (int kt = 0; kt < 2; kt++) {
        __syncthreads();
#pragma unroll
        for (int t = 0; t < 8; t++) {
            int idx = tid + 256 * t;
            int row = idx >> 4, cc = idx & 15;
            *(uint4*)&As[row*136 + cc*8] =
                reinterpret_cast<const uint4*>(g_oh)[(size_t)(bm*128+row)*32 + kt*16 + cc];
        }
#pragma unroll
        for (int t = 0; t < 8; t++) {
            int idx = tid + 256 * t;
            int row = idx >> 4, cc = idx & 15;
            *(uint4*)&Bs[row*136 + cc*8] =
                reinterpret_cast<const uint4*>(g_Wot)[(size_t)row*32 + kt*16 + cc];
        }
        __syncthreads();
#pragma unroll
        for (int ki = 0; ki < 8; ki++) {
            uint32_t a[2][4];
#pragma unroll
            for (int mt = 0; mt < 2; mt++)
                ldm_x4(a[mt], qaddr<136>(asb, wm + mt*16, ki*16, lane));
#pragma unroll
            for (int nf = 0; nf < 4; nf++) {
                uint32_t b[4];
                ldm_x4(b, qaddr<136>(bsb, wn + nf*16, ki*16, lane));
                uint32_t b0[2] = {b[0], b[2]}, b1[2] = {b[1], b[3]};
#pragma unroll
                for (int mt = 0; mt < 2; mt++) {
                    mma_f16(c[mt][nf*2],   a[mt], b0);
                    mma_f16(c[mt][nf*2+1], a[mt], b1);
                }
            }
        }
    }
#pragma unroll
    for (int mt = 0; mt < 2; mt++) {
#pragma unroll
        for (int rs = 0; rs < 2; rs++) {
            int m = bm*128 + wm + mt*16 + g + rs*8;
            float mk = mask[m];
#pragma unroll
            for (int ni = 0; ni < 8; ni++) {
                int col = wn + ni*8 + tig*2;
                float2 b2 = *(const float2*)(bo + col);
                float2 o2 = make_float2((c[mt][ni][rs*2+0] + b2.x) * mk,
                                        (c[mt][ni][rs*2+1] + b2.y) * mk);
                *(float2*)(out + (size_t)m * 128 + col) = o2;
            }
        }
    }
}

// ---------------- launch ----------------
extern "C" void kernel_launch(void* const* d_in, const int* in_sizes, int n_in,
                              void* d_out, int out_size) {
    const float* pair_rep = (const float*)d_in[0];
    const float* mask     = (const float*)d_in[1];
    const float* gamma    = (const float*)d_in[2];
    const float* beta     = (const float*)d_in[3];
    const float* Wq       = (const float*)d_in[4];
    const float* Wk       = (const float*)d_in[5];
    const float* Wv       = (const float*)d_in[6];
    const float* Wb       = (const float*)d_in[7];
    const float* Wu       = (const float*)d_in[8];
    const float* bu       = (const float*)d_in[9];
    const float* Wo       = (const float*)d_in[10];
    const float* bo       = (const float*)d_in[11];
    float* out = (float*)d_out;

    cudaFuncSetAttribute(attn_kernel, cudaFuncAttributeMaxDynamicSharedMemorySize, ATTN_SMEM);
    cudaFuncSetAttribute(proj_split_kernel, cudaFuncAttributeMaxDynamicSharedMemorySize, PROJS_SMEM);
    cudaFuncSetAttribute(proj_single_kernel, cudaFuncAttributeMaxDynamicSharedMemorySize, PROJ1_SMEM);
    cudaFuncSetAttribute(out_kernel, cudaFuncAttributeMaxDynamicSharedMemorySize, OUT_SMEM);

    prep_kernel<<<64, 256>>>(Wq, Wk, Wv, Wu, Wo);
    ln_kernel<<<8192, 256>>>(pair_rep, gamma, beta, Wb, mask);
    proj_split_kernel<<<dim3(512, 8), 256, PROJS_SMEM>>>();
    proj_single_kernel<<<dim3(512, 4), 256, PROJ1_SMEM>>>(bu);
    attn_kernel<<<4096, 512, ATTN_SMEM>>>();
    out_kernel<<<512, 256, OUT_SMEM>>>(bo, mask, out);
}

// round 17
// speedup vs baseline: 1.0228x; 1.0228x over previous
#include <cuda_runtime.h>
#include <cuda_fp16.h>
#include <cstdint>

#define LL 256
#define HC 256
#define NROWS (LL*LL)   // 65536

// ---------------- scratch (static device globals; no allocations) ----------
__device__ __align__(16) __half g_xs[NROWS*256];      // layernorm out split: [row][0:128 hi | 128:256 lo]
__device__ __align__(16) __half g_qs[NROWS*512];      // q split  [(s,h,r)][0:64 hi | 64:128 lo] (pre-scaled)
__device__ __align__(16) __half g_ks[NROWS*512];      // k split  same layout
__device__ __align__(16) __half g_vh[NROWS*256];      // v half   [(s,h,r)][c]
__device__ __align__(16) __half g_uh[NROWS*256];      // sigmoid gate half [(s,h,r)][c]
__device__ __align__(16) float  g_bias[4*NROWS];      // pair_bias + mask bias [h][q][v]
__device__ __align__(16) __half g_oh[NROWS*256];      // attention out half [s*256+q][h*64+c]
// pre-transposed / split weights [n][k] half
__device__ __align__(16) __half g_Wqt_h[256*128], g_Wqt_l[256*128];
__device__ __align__(16) __half g_Wkt_h[256*128], g_Wkt_l[256*128];
__device__ __align__(16) __half g_Wvt[256*128], g_Wut[256*128];
__device__ __align__(16) __half g_Wot[128*256];

// ---------------- mma / ldmatrix helpers ----------------
__device__ __forceinline__ uint32_t sm_addr(const void* p) {
    return (uint32_t)__cvta_generic_to_shared(p);
}
__device__ __forceinline__ void ldm_x4(uint32_t* r, uint32_t a) {
    asm volatile("ldmatrix.sync.aligned.m8n8.x4.shared.b16 {%0,%1,%2,%3}, [%4];"
                 : "=r"(r[0]), "=r"(r[1]), "=r"(r[2]), "=r"(r[3]) : "r"(a));
}
__device__ __forceinline__ void ldm_x4_t(uint32_t* r, uint32_t a) {
    asm volatile("ldmatrix.sync.aligned.m8n8.x4.trans.shared.b16 {%0,%1,%2,%3}, [%4];"
                 : "=r"(r[0]), "=r"(r[1]), "=r"(r[2]), "=r"(r[3]) : "r"(a));
}
__device__ __forceinline__ void mma_f16(float* c, const uint32_t* a, const uint32_t* b) {
    asm volatile("mma.sync.aligned.m16n8k16.row.col.f32.f16.f16.f32 "
                 "{%0,%1,%2,%3},{%4,%5,%6,%7},{%8,%9},{%0,%1,%2,%3};"
                 : "+f"(c[0]), "+f"(c[1]), "+f"(c[2]), "+f"(c[3])
                 : "r"(a[0]), "r"(a[1]), "r"(a[2]), "r"(a[3]), "r"(b[0]), "r"(b[1]));
}
template<int STRIDE>
__device__ __forceinline__ uint32_t qaddr(uint32_t base, int r0, int c0, int lane) {
    int t = lane >> 3, tr = lane & 7;
    return base + (uint32_t)(((r0 + tr + (t & 1) * 8) * STRIDE + c0 + (t >> 1) * 8) * 2);
}
__device__ __forceinline__ uint32_t pack2(float x, float y) {
    __half2 h = __floats2half2_rn(x, y);
    return *(uint32_t*)&h;
}

// ---------------- kernel 0: weight transpose + split ----------------
__global__ void prep_kernel(const float* __restrict__ Wq, const float* __restrict__ Wk,
                            const float* __restrict__ Wv, const float* __restrict__ Wu,
                            const float* __restrict__ Wo) {
    for (int idx = blockIdx.x * 256 + threadIdx.x; idx < 32768; idx += gridDim.x * 256) {
        int k = idx >> 8, n = idx & 255;
        float xq = Wq[idx]; __half hq = __float2half_rn(xq);
        g_Wqt_h[n*128+k] = hq; g_Wqt_l[n*128+k] = __float2half_rn(xq - __half2float(hq));
        float xk = Wk[idx]; __half hk = __float2half_rn(xk);
        g_Wkt_h[n*128+k] = hk; g_Wkt_l[n*128+k] = __float2half_rn(xk - __half2float(hk));
        g_Wvt[n*128+k] = __float2half_rn(Wv[idx]);
        g_Wut[n*128+k] = __float2half_rn(Wu[idx]);
        int k2 = idx >> 7, n2 = idx & 127;
        g_Wot[n2*256+k2] = __float2half_rn(Wo[idx]);
    }
}

// ---------------- kernel 1: layernorm + fused pair_bias/mask bias ----------
__global__ __launch_bounds__(256) void ln_kernel(const float* __restrict__ in,
                                                 const float* __restrict__ gamma,
                                                 const float* __restrict__ beta,
                                                 const float* __restrict__ Wb,
                                                 const float* __restrict__ mask) {
    int row  = blockIdx.x * 8 + (threadIdx.x >> 5);
    int lane = threadIdx.x & 31;
    float4 v = reinterpret_cast<const float4*>(in)[(size_t)row * 32 + lane];
    float s  = v.x + v.y + v.z + v.w;
    float ss = v.x*v.x + v.y*v.y + v.z*v.z + v.w*v.w;
#pragma unroll
    for (int o = 16; o; o >>= 1) {
        s  += __shfl_xor_sync(0xffffffffu, s,  o);
        ss += __shfl_xor_sync(0xffffffffu, ss, o);
    }
    float mu  = s * (1.f / 128.f);
    float var = fmaxf(ss * (1.f / 128.f) - mu * mu, 0.f);
    float inv = rsqrtf(var + 1e-5f);
    float4 g = reinterpret_cast<const float4*>(gamma)[lane];
    float4 b = reinterpret_cast<const float4*>(beta)[lane];
    float o4[4];
    o4[0] = (v.x - mu) * inv * g.x + b.x;
    o4[1] = (v.y - mu) * inv * g.y + b.y;
    o4[2] = (v.z - mu) * inv * g.z + b.z;
    o4[3] = (v.w - mu) * inv * g.w + b.w;
    // split-half output
    __half h[4]; float l[4];
#pragma unroll
    for (int i = 0; i < 4; i++) { h[i] = __float2half_rn(o4[i]); l[i] = o4[i] - __half2float(h[i]); }
    uint2 hi2 = make_uint2(pack2(__half2float(h[0]), __half2float(h[1])),
                           pack2(__half2float(h[2]), __half2float(h[3])));
    uint2 lo2 = make_uint2(pack2(l[0], l[1]), pack2(l[2], l[3]));
    uint2* dst = (uint2*)(g_xs + (size_t)row * 256);
    dst[lane] = hi2;
    dst[32 + lane] = lo2;
    // fused pair_bias: b_h = sum_d x[d] * Wb[d*4+h], warp-reduced
    int d0 = lane * 4;
    float4 w0 = *(const float4*)(Wb + (d0+0)*4);
    float4 w1 = *(const float4*)(Wb + (d0+1)*4);
    float4 w2 = *(const float4*)(Wb + (d0+2)*4);
    float4 w3 = *(const float4*)(Wb + (d0+3)*4);
    float b0 = o4[0]*w0.x + o4[1]*w1.x + o4[2]*w2.x + o4[3]*w3.x;
    float b1 = o4[0]*w0.y + o4[1]*w1.y + o4[2]*w2.y + o4[3]*w3.y;
    float b2 = o4[0]*w0.z + o4[1]*w1.z + o4[2]*w2.z + o4[3]*w3.z;
    float b3 = o4[0]*w0.w + o4[1]*w1.w + o4[2]*w2.w + o4[3]*w3.w;
#pragma unroll
    for (int o = 16; o; o >>= 1) {
        b0 += __shfl_xor_sync(0xffffffffu, b0, o);
        b1 += __shfl_xor_sync(0xffffffffu, b1, o);
        b2 += __shfl_xor_sync(0xffffffffu, b2, o);
        b3 += __shfl_xor_sync(0xffffffffu, b3, o);
    }
    if (lane < 4) {
        float bsel = (lane == 0) ? b0 : (lane == 1) ? b1 : (lane == 2) ? b2 : b3;
        g_bias[(size_t)lane * 65536 + row] = bsel + 1e9f * (mask[row] - 1.f);
    }
}

// ---------------- kernel 3: split projection GEMM (Q,K) -- R10 form ----------
// CTA tile 128m x 64n, FULL K=128 resident (hi|lo). One sync, 8 k-steps.
#define PROJS_SMEM (128*264*2 + 2*64*136*2)   // 67584 + 34816 = 102400
__global__ __launch_bounds__(256) void proj_split_kernel() {
    extern __shared__ char smem[];
    __half* As = (__half*)smem;                       // [128][264]: 0..127 hi k, 128..255 lo k
    __half* Bh = (__half*)(smem + 128*264*2);         // [64][136]
    __half* Bl = (__half*)(smem + 128*264*2 + 64*136*2);
    int bm = blockIdx.x, bn = blockIdx.y;             // bn 0..7
    int mat = bn >> 2;                                // 0:q 1:k
    int ncol0 = (bn & 3) * 64;
    const __half* Wh = mat ? g_Wkt_h : g_Wqt_h;
    const __half* Wl = mat ? g_Wkt_l : g_Wqt_l;
    int tid = threadIdx.x, lane = tid & 31, w = tid >> 5;
    int g = lane >> 2, tig = lane & 3;
    int wm = (w & 3) * 32, wn = (w >> 2) * 32;
    uint32_t asb = sm_addr(As), bhb = sm_addr(Bh), blb = sm_addr(Bl);

    // A: 128 rows x 32 uint4 (row layout identical to g_xs)
#pragma unroll
    for (int t = 0; t < 16; t++) {
        int idx = tid + 256 * t;
        int row = idx >> 5, cc = idx & 31;
        *(uint4*)&As[row*264 + cc*8] =
            reinterpret_cast<const uint4*>(g_xs)[(size_t)(bm*128+row)*32 + cc];
    }
    // B: 64 rows x 16 uint4 each of hi/lo
#pragma unroll
    for (int t = 0; t < 4; t++) {
        int idx = tid + 256 * t;
        int row = idx >> 4, cc = idx & 15;
        *(uint4*)&Bh[row*136 + cc*8] =
            reinterpret_cast<const uint4*>(Wh)[(size_t)(ncol0+row)*16 + cc];
        *(uint4*)&Bl[row*136 + cc*8] =
            reinterpret_cast<const uint4*>(Wl)[(size_t)(ncol0+row)*16 + cc];
    }
    __syncthreads();

    float c[2][4][4] = {};
#pragma unroll
    for (int ki = 0; ki < 8; ki++) {
        uint32_t ah[2][4], al[2][4];
#pragma unroll
        for (int mt = 0; mt < 2; mt++) {
            ldm_x4(ah[mt], qaddr<264>(asb, wm + mt*16, ki*16, lane));
            ldm_x4(al[mt], qaddr<264>(asb, wm + mt*16, 128 + ki*16, lane));
        }
#pragma unroll
        for (int nf = 0; nf < 2; nf++) {
            uint32_t bh[4], bl[4];
            ldm_x4(bh, qaddr<136>(bhb, wn + nf*16, ki*16, lane));
            ldm_x4(bl, qaddr<136>(blb, wn + nf*16, ki*16, lane));
            uint32_t b0h[2] = {bh[0], bh[2]}, b1h[2] = {bh[1], bh[3]};
            uint32_t b0l[2] = {bl[0], bl[2]}, b1l[2] = {bl[1], bl[3]};
#pragma unroll
            for (int mt = 0; mt < 2; mt++) {
                mma_f16(c[mt][nf*2],   ah[mt], b0h);
                mma_f16(c[mt][nf*2],   al[mt], b0h);
                mma_f16(c[mt][nf*2],   ah[mt], b0l);
                mma_f16(c[mt][nf*2+1], ah[mt], b1h);
                mma_f16(c[mt][nf*2+1], al[mt], b1h);
                mma_f16(c[mt][nf*2+1], ah[mt], b1l);
            }
        }
    }
    // epilogue: split fp32 -> (hi,lo) half pairs, scatter to [s,h,r,c] layout
    __half* dst = mat ? g_ks : g_qs;
    float scale = mat ? 1.f : 0.125f;
#pragma unroll
    for (int mt = 0; mt < 2; mt++) {
#pragma unroll
        for (int rs = 0; rs < 2; rs++) {
            int m = bm*128 + wm + mt*16 + g + rs*8;
            int si = m >> 8, rr = m & 255;
#pragma unroll
            for (int ni = 0; ni < 4; ni++) {
                int col = ncol0 + wn + ni*8 + tig*2;
                int head = col >> 6, cc = col & 63;
                size_t drow = ((size_t)(si*4 + head))*256 + rr;
                float v0 = c[mt][ni][rs*2+0] * scale;
                float v1 = c[mt][ni][rs*2+1] * scale;
                __half h0 = __float2half_rn(v0), h1 = __float2half_rn(v1);
                float l0 = v0 - __half2float(h0), l1 = v1 - __half2float(h1);
                *(uint32_t*)(dst + drow*128 + cc)      = pack2(__half2float(h0), __half2float(h1));
                *(uint32_t*)(dst + drow*128 + 64 + cc) = pack2(l0, l1);
            }
        }
    }
}

// ---------------- kernel 4: single-fp16 projection GEMM (V,U) ----------------
// CTA tile 128x128, FULL K=128 resident, one tile per CTA (grid 512x4), natural regs.
#define PROJ1_SMEM (2*128*136*2)   // 69632
__global__ __launch_bounds__(256) void proj_single_kernel(const float* __restrict__ bu) {
    extern __shared__ char smem[];
    __half* As = (__half*)smem;                   // [128][136]
    __half* Bs = (__half*)(smem + 128*136*2);     // [128][136]
    int bm = blockIdx.x, bn = blockIdx.y;
    int mat = bn >> 1;                  // 0:v 1:u
    int ncol0 = (bn & 1) * 128;
    const __half* W = mat ? g_Wut : g_Wvt;
    int tid = threadIdx.x, lane = tid & 31, w = tid >> 5;
    int g = lane >> 2, tig = lane & 3;
    int wm = (w & 3) * 32, wn = (w >> 2) * 64;
    uint32_t asb = sm_addr(As), bsb = sm_addr(Bs);

#pragma unroll
    for (int t = 0; t < 8; t++) {
        int idx = tid + 256 * t;
        int row = idx >> 4, cc = idx & 15;
        *(uint4*)&As[row*136 + cc*8] =
            reinterpret_cast<const uint4*>(g_xs)[(size_t)(bm*128+row)*32 + cc];   // hi half only
        *(uint4*)&Bs[row*136 + cc*8] =
            reinterpret_cast<const uint4*>(W)[(size_t)(ncol0+row)*16 + cc];
    }
    __syncthreads();

    float c[2][8][4] = {};
#pragma unroll
    for (int ki = 0; ki < 8; ki++) {
        uint32_t a[2][4];
#pragma unroll
        for (int mt = 0; mt < 2; mt++)
            ldm_x4(a[mt], qaddr<136>(asb, wm + mt*16, ki*16, lane));
#pragma unroll
        for (int nf = 0; nf < 4; nf++) {
            uint32_t b[4];
            ldm_x4(b, qaddr<136>(bsb, wn + nf*16, ki*16, lane));
            uint32_t b0[2] = {b[0], b[2]}, b1[2] = {b[1], b[3]};
#pragma unroll
            for (int mt = 0; mt < 2; mt++) {
                mma_f16(c[mt][nf*2],   a[mt], b0);
                mma_f16(c[mt][nf*2+1], a[mt], b1);
            }
        }
    }
#pragma unroll
    for (int mt = 0; mt < 2; mt++) {
#pragma unroll
        for (int rs = 0; rs < 2; rs++) {
            int m = bm*128 + wm + mt*16 + g + rs*8;
            int si = m >> 8, rr = m & 255;
#pragma unroll
            for (int ni = 0; ni < 8; ni++) {
                int col = ncol0 + wn + ni*8 + tig*2;
                int head = col >> 6, cc = col & 63;
                size_t drow = ((size_t)(si*4 + head))*256 + rr;
                float v0 = c[mt][ni][rs*2+0], v1 = c[mt][ni][rs*2+1];
                if (mat == 0) {
                    *(uint32_t*)(g_vh + drow*64 + cc) = pack2(v0, v1);
                } else {
                    float2 b2 = *(const float2*)(bu + col);
                    float u0 = 1.f / (1.f + __expf(-(v0 + b2.x)));
                    float u1 = 1.f / (1.f + __expf(-(v1 + b2.y)));
                    *(uint32_t*)(g_uh + drow*64 + cc) = pack2(u0, u1);
                }
            }
        }
    }
}

// ---------------- kernel 5: attention per (s, h, q-tile of 64) ----------------
// smem 91.4KB -> 2 CTAs/SM.
#define AT_QB 17408
#define AT_PH 17408
#define AT_VS 52224
#define AT_WM 89088
#define AT_WS 90112
#define AT_RI 91136
#define ATTN_SMEM 91392
__global__ __launch_bounds__(512, 2) void attn_kernel() {
    extern __shared__ char smem[];
    __half* Ks = (__half*)smem;
    __half* Qb = (__half*)(smem + AT_QB);
    __half* Ph = (__half*)(smem + AT_PH);
    __half* Vs = (__half*)(smem + AT_VS);
    float* wmax = (float*)(smem + AT_WM);
    float* wsum = (float*)(smem + AT_WS);
    float* rinv = (float*)(smem + AT_RI);

    int b = blockIdx.x;
    int s = b >> 4, h = (b >> 2) & 3, qt = b & 3;
    int tid = threadIdx.x, lane = tid & 31, w = tid >> 5;
    int g = lane >> 2, tig = lane & 3;
    size_t base = ((size_t)(s*4 + h)) * 256;

#pragma unroll
    for (int t = 0; t < 2; t++) {
        int idx = tid + 512 * t;
        int r = idx >> 4, cc = idx & 15;
        *(uint4*)&Ks[r*136 + cc*8] =
            reinterpret_cast<const uint4*>(g_ks)[(base + qt*64 + r)*16 + cc];
    }

    int wq = w & 3, wv = w >> 2;
    int q0 = wq * 16;
    uint32_t ksb = sm_addr(Ks), qbb = sm_addr(Qb);
    float c[8][4] = {};
#pragma unroll
    for (int p = 0; p < 2; p++) {
        if (p) __syncthreads();
#pragma unroll
        for (int t = 0; t < 4; t++) {
            int idx = tid + 512 * t;
            int r = idx >> 4, cc = idx & 15;
            *(uint4*)&Qb[r*136 + cc*8] =
                reinterpret_cast<const uint4*>(g_qs)[(base + p*128 + r)*16 + cc];
        }
        __syncthreads();
#pragma unroll
        for (int kt = 0; kt < 4; kt++) {
            uint32_t ah[4], al[4];
            ldm_x4(ah, qaddr<136>(ksb, q0, kt*16, lane));
            ldm_x4(al, qaddr<136>(ksb, q0, 64 + kt*16, lane));
#pragma unroll
            for (int nf = 0; nf < 2; nf++) {
                uint32_t bh[4], bl[4];
                ldm_x4(bh, qaddr<136>(qbb, wv*32 + nf*16, kt*16, lane));
                ldm_x4(bl, qaddr<136>(qbb, wv*32 + nf*16, 64 + kt*16, lane));
                uint32_t b0h[2] = {bh[0], bh[2]}, b1h[2] = {bh[1], bh[3]};
                uint32_t b0l[2] = {bl[0], bl[2]}, b1l[2] = {bl[1], bl[3]};
                mma_f16(c[p*4 + nf*2],   ah, b0h);
                mma_f16(c[p*4 + nf*2],   al, b0h);
                mma_f16(c[p*4 + nf*2],   ah, b0l);
                mma_f16(c[p*4 + nf*2+1], ah, b1h);
                mma_f16(c[p*4 + nf*2+1], al, b1h);
                mma_f16(c[p*4 + nf*2+1], ah, b1l);
            }
        }
    }

    const float* bp = g_bias + ((size_t)h*256 + qt*64 + q0) * 256;
    float m0 = -3e38f, m1 = -3e38f;
#pragma unroll
    for (int ni = 0; ni < 8; ni++) {
        int v = (ni >> 2)*128 + wv*32 + (ni & 3)*8 + tig*2;
        float2 b0 = *(const float2*)(bp + (size_t)g*256 + v);
        float2 b1 = *(const float2*)(bp + (size_t)(g+8)*256 + v);
        c[ni][0] += b0.x; c[ni][1] += b0.y; c[ni][2] += b1.x; c[ni][3] += b1.y;
        m0 = fmaxf(m0, fmaxf(c[ni][0], c[ni][1]));
        m1 = fmaxf(m1, fmaxf(c[ni][2], c[ni][3]));
    }
    m0 = fmaxf(m0, __shfl_xor_sync(~0u, m0, 1)); m0 = fmaxf(m0, __shfl_xor_sync(~0u, m0, 2));
    m1 = fmaxf(m1, __shfl_xor_sync(~0u, m1, 1)); m1 = fmaxf(m1, __shfl_xor_sync(~0u, m1, 2));
    if (tig == 0) { wmax[wv*64 + q0 + g] = m0; wmax[wv*64 + q0 + g + 8] = m1; }
    __syncthreads();

#pragma unroll
    for (int t = 0; t < 4; t++) {
        int idx = tid + 512 * t;
        int r = idx >> 3, cc = idx & 7;
        *(uint4*)&Vs[r*72 + cc*8] =
            reinterpret_cast<const uint4*>(g_vh)[(base + r)*8 + cc];
    }

    float M0 = fmaxf(fmaxf(wmax[q0+g],     wmax[64+q0+g]),
                     fmaxf(wmax[128+q0+g], wmax[192+q0+g]));
    float M1 = fmaxf(fmaxf(wmax[q0+g+8],     wmax[64+q0+g+8]),
                     fmaxf(wmax[128+q0+g+8], wmax[192+q0+g+8]));
    float s0 = 0.f, s1 = 0.f;
#pragma unroll
    for (int ni = 0; ni < 8; ni++) {
        c[ni][0] = __expf(c[ni][0] - M0); c[ni][1] = __expf(c[ni][1] - M0);
        c[ni][2] = __expf(c[ni][2] - M1); c[ni][3] = __expf(c[ni][3] - M1);
        s0 += c[ni][0] + c[ni][1];
        s1 += c[ni][2] + c[ni][3];
        int v = (ni >> 2)*128 + wv*32 + (ni & 3)*8 + tig*2;
        *(uint32_t*)&Ph[(q0+g)*264 + v]   = pack2(c[ni][0], c[ni][1]);
        *(uint32_t*)&Ph[(q0+g+8)*264 + v] = pack2(c[ni][2], c[ni][3]);
    }
    s0 += __shfl_xor_sync(~0u, s0, 1); s0 += __shfl_xor_sync(~0u, s0, 2);
    s1 += __shfl_xor_sync(~0u, s1, 1); s1 += __shfl_xor_sync(~0u, s1, 2);
    if (tig == 0) { wsum[wv*64 + q0 + g] = s0; wsum[wv*64 + q0 + g + 8] = s1; }
    __syncthreads();
    if (tid < 64)
        rinv[tid] = 1.f / (wsum[tid] + wsum[64+tid] + wsum[128+tid] + wsum[192+tid]);
    __syncthreads();

    int wq2 = w & 3, wc = w >> 2;
    int pq0 = wq2 * 16, c0 = wc * 16;
    uint32_t phb = sm_addr(Ph), vsb = sm_addr(Vs);
    float oc[2][4] = {};
#pragma unroll
    for (int kt = 0; kt < 16; kt++) {
        uint32_t a[4], bt[4];
        ldm_x4(a, qaddr<264>(phb, pq0, kt*16, lane));
        ldm_x4_t(bt, qaddr<72>(vsb, kt*16, c0, lane));
        uint32_t f0[2] = {bt[0], bt[1]}, f1[2] = {bt[2], bt[3]};
        mma_f16(oc[0], a, f0);
        mma_f16(oc[1], a, f1);
    }
    {
        float rv0 = rinv[pq0 + g], rv1 = rinv[pq0 + g + 8];
        int qgA = qt*64 + pq0 + g, qgB = qgA + 8;
#pragma unroll
        for (int j = 0; j < 2; j++) {
            int ccol = c0 + j*8 + tig*2;
            float2 u0 = __half22float2(*(const __half2*)(g_uh + (base + qgA)*64 + ccol));
            float2 u1 = __half22float2(*(const __half2*)(g_uh + (base + qgB)*64 + ccol));
            float oA0 = oc[j][0] * rv0 * u0.x;
            float oA1 = oc[j][1] * rv0 * u0.y;
            float oB0 = oc[j][2] * rv1 * u1.x;
            float oB1 = oc[j][3] * rv1 * u1.y;
            *(uint32_t*)(g_oh + ((size_t)(s*256 + qgA))*256 + h*64 + ccol) = pack2(oA0, oA1);
            *(uint32_t*)(g_oh + ((size_t)(s*256 + qgB))*256 + h*64 + ccol) = pack2(oB0, oB1);
        }
    }
}

// ---------------- kernel 6: output GEMM (single fp16, half A input) ----------
#define OUT_SMEM (128*136*2*2)
__global__ __launch_bounds__(256) void out_kernel(const float* __restrict__ bo,
                                                  const float* __restrict__ mask,
                                                  float* __restrict__ out) {
    extern __shared__ char smem[];
    __half* As = (__half*)smem;                  // [128][136]
    __half* Bs = (__half*)(smem + 128*136*2);    // [128][136]
    int bm = blockIdx.x;
    int tid = threadIdx.x, lane = tid & 31, w = tid >> 5;
    int g = lane >> 2, tig = lane & 3;
    int wm = (w & 3) * 32, wn = (w >> 2) * 64;
    uint32_t asb = sm_addr(As), bsb = sm_addr(Bs);
    float c[2][8][4] = {};
    for (int kt = 0; kt < 2; kt++) {
        __syncthreads();
#pragma unroll
        for (int t = 0; t < 8; t++) {
            int idx = tid + 256 * t;
            int row = idx >> 4, cc = idx & 15;
            *(uint4*)&As[row*136 + cc*8] =
                reinterpret_cast<const uint4*>(g_oh)[(size_t)(bm*128+row)*32 + kt*16 + cc];
        }
#pragma unroll
        for (int t = 0; t < 8; t++) {
            int idx = tid + 256 * t;
            int row = idx >> 4, cc = idx & 15;
            *(uint4*)&Bs[row*136 + cc*8] =
                reinterpret_cast<const uint4*>(g_Wot)[(size_t)row*32 + kt*16 + cc];
        }
        __syncthreads();
#pragma unroll
        for (int ki = 0; ki < 8; ki++) {
            uint32_t a[2][4];
#pragma unroll
            for (int mt = 0; mt < 2; mt++)
                ldm_x4(a[mt], qaddr<136>(asb, wm + mt*16, ki*16, lane));
#pragma unroll
            for (int nf = 0; nf < 4; nf++) {
                uint32_t b[4];
                ldm_x4(b, qaddr<136>(bsb, wn + nf*16, ki*16, lane));
                uint32_t b0[2] = {b[0], b[2]}, b1[2] = {b[1], b[3]};
#pragma unroll
                for (int mt = 0; mt < 2; mt++) {
                    mma_f16(c[mt][nf*2],   a[mt], b0);
                    mma_f16(c[mt][nf*2+1], a[mt], b1);
                }
            }
        }
    }
#pragma unroll
    for (int mt = 0; mt < 2; mt++) {
#pragma unroll
        for (int rs = 0; rs < 2; rs++) {
            int m = bm*128 + wm + mt*16 + g + rs*8;
            float mk = mask[m];
#pragma unroll
            for (int ni = 0; ni < 8; ni++) {
                int col = wn + ni*8 + tig*2;
                float2 b2 = *(const float2*)(bo + col);
                float2 o2 = make_float2((c[mt][ni][rs*2+0] + b2.x) * mk,
                                        (c[mt][ni][rs*2+1] + b2.y) * mk);
                *(float2*)(out + (size_t)m * 128 + col) = o2;
            }
        }
    }
}

// ---------------- launch ----------------
extern "C" void kernel_launch(void* const* d_in, const int* in_sizes, int n_in,
                              void* d_out, int out_size) {
    const float* pair_rep = (const float*)d_in[0];
    const float* mask     = (const float*)d_in[1];
    const float* gamma    = (const float*)d_in[2];
    const float* beta     = (const float*)d_in[3];
    const float* Wq       = (const float*)d_in[4];
    const float* Wk       = (const float*)d_in[5];
    const float* Wv       = (const float*)d_in[6];
    const float* Wb       = (const float*)d_in[7];
    const float* Wu       = (const float*)d_in[8];
    const float* bu       = (const float*)d_in[9];
    const float* Wo       = (const float*)d_in[10];
    const float* bo       = (const float*)d_in[11];
    float* out = (float*)d_out;

    cudaFuncSetAttribute(attn_kernel, cudaFuncAttributeMaxDynamicSharedMemorySize, ATTN_SMEM);
    cudaFuncSetAttribute(proj_split_kernel, cudaFuncAttributeMaxDynamicSharedMemorySize, PROJS_SMEM);
    cudaFuncSetAttribute(proj_single_kernel, cudaFuncAttributeMaxDynamicSharedMemorySize, PROJ1_SMEM);
    cudaFuncSetAttribute(out_kernel, cudaFuncAttributeMaxDynamicSharedMemorySize, OUT_SMEM);

    prep_kernel<<<64, 256>>>(Wq, Wk, Wv, Wu, Wo);
    ln_kernel<<<8192, 256>>>(pair_rep, gamma, beta, Wb, mask);
    proj_split_kernel<<<dim3(512, 8), 256, PROJS_SMEM>>>();
    proj_single_kernel<<<dim3(512, 4), 256, PROJ1_SMEM>>>(bu);
    attn_kernel<<<4096, 512, ATTN_SMEM>>>();
    out_kernel<<<512, 256, OUT_SMEM>>>(bo, mask, out);
}